// round 8
// baseline (speedup 1.0000x reference)
#include <cuda_runtime.h>
#include <cuda_bf16.h>
#include <math.h>
#include <stdint.h>

#define NBATCH 32
#define NHEAD  8
#define SEQ    512
#define HD     64

constexpr size_t V_SIZE   = (size_t)NBATCH * SEQ * NHEAD * HD;     // 8388608
constexpr size_t SER_SIZE = (size_t)NBATCH * NHEAD * SEQ * SEQ;    // 67108864

// ---- prepacked fragment arrays (bf16 hi/lo, mma-fragment-major) ----
__device__ uint32_t d_KB[(size_t)256 * 64 * 4 * 32 * 4];
__device__ uint32_t d_VB[(size_t)256 * 8 * 32 * 32 * 4];

constexpr int KBN = 256 * 64 * 4 * 32;
constexpr int VBN = 256 * 8 * 32 * 32;
constexpr int PREN = KBN + VBN;

// ---- smem layout (bytes) ----
constexpr uint32_t A_OFF  = 0;        // 8 * 8192  = 65536 (per-warp double buffer; V-partials later)
constexpr uint32_t B_OFF  = 65536;    // 8 * 4096  = 32768 (per-warp P-frag stash)
constexpr uint32_t RS_OFF = 98304;    // [16 rows][8 warps] f32
constexpr uint32_t INV_OFF = 98816;   // [16] f32
constexpr uint32_t SMEM_BYTES = 98944;

__device__ __forceinline__ uint32_t s2u(const void* p) {
    uint32_t a;
    asm("{ .reg .u64 t; cvta.to.shared.u64 t, %1; cvt.u32.u64 %0, t; }" : "=r"(a) : "l"(p));
    return a;
}
__device__ __forceinline__ void cp16(uint32_t dst, const void* src) {
    asm volatile("cp.async.cg.shared.global [%0], [%1], 16;" :: "r"(dst), "l"(src) : "memory");
}
__device__ __forceinline__ void cpcommit() {
    asm volatile("cp.async.commit_group;" ::: "memory");
}
__device__ __forceinline__ void cpwait0() {
    asm volatile("cp.async.wait_group 0;" ::: "memory");
}
__device__ __forceinline__ void cpwait1() {
    asm volatile("cp.async.wait_group 1;" ::: "memory");
}

__device__ __forceinline__ void packhl(float x0, float x1, uint32_t& hi, uint32_t& lo) {
    __nv_bfloat16 h0 = __float2bfloat16(x0);
    __nv_bfloat16 h1 = __float2bfloat16(x1);
    __nv_bfloat16 l0 = __float2bfloat16(x0 - __bfloat162float(h0));
    __nv_bfloat16 l1 = __float2bfloat16(x1 - __bfloat162float(h1));
    hi = (uint32_t)__bfloat16_as_ushort(h0) | ((uint32_t)__bfloat16_as_ushort(h1) << 16);
    lo = (uint32_t)__bfloat16_as_ushort(l0) | ((uint32_t)__bfloat16_as_ushort(l1) << 16);
}

__device__ __forceinline__ void mma_bf16(float* c, const uint32_t* a, uint32_t b0, uint32_t b1) {
    asm volatile(
        "mma.sync.aligned.m16n8k16.row.col.f32.bf16.bf16.f32 "
        "{%0,%1,%2,%3},{%4,%5,%6,%7},{%8,%9},{%0,%1,%2,%3};\n"
        : "+f"(c[0]), "+f"(c[1]), "+f"(c[2]), "+f"(c[3])
        : "r"(a[0]), "r"(a[1]), "r"(a[2]), "r"(a[3]), "r"(b0), "r"(b1));
}

__device__ __forceinline__ float2 serpair(uint32_t Hv, uint32_t Lv, float inv) {
    return make_float2(
        (__uint_as_float(Hv << 16) + __uint_as_float(Lv << 16)) * inv,
        (__uint_as_float(Hv & 0xffff0000u) + __uint_as_float(Lv & 0xffff0000u)) * inv);
}

// ---------------- prepack: K and V fragments only (Q handled in main) ----------------
__global__ void __launch_bounds__(256) prepack(const float* __restrict__ K,
                                               const float* __restrict__ V) {
    int idx = blockIdx.x * 256 + threadIdx.x;
    int g = (idx >> 2) & 7, t = idx & 3;
    uint32_t h0, l0, h1, l1;
    if (idx < KBN) {
        int kt = (idx >> 5) & 3, st = (idx >> 7) & 63, bh = idx >> 13;
        int b = bh >> 3, h = bh & 7;
        int s = st * 8 + g, e0 = kt * 16 + 2 * t;
        const float* kp = K + (((size_t)b * SEQ + s) * NHEAD + h) * HD;
        packhl(kp[e0],     kp[e0 + 1], h0, l0);
        packhl(kp[e0 + 8], kp[e0 + 9], h1, l1);
        *(uint4*)(d_KB + (size_t)idx * 4) = make_uint4(h0, h1, l0, l1);
    } else if (idx < PREN) {
        int i = idx - KBN;
        int st = (i >> 5) & 31, dt = (i >> 10) & 7, bh = i >> 13;
        int b = bh >> 3, h = bh & 7;
        int s0 = st * 16 + 2 * t, d = dt * 8 + g;
        const float* vp = V + ((size_t)b * SEQ * NHEAD + h) * HD + d;
        packhl(vp[(size_t)s0 * 512],       vp[(size_t)(s0 + 1) * 512], h0, l0);
        packhl(vp[(size_t)(s0 + 8) * 512], vp[(size_t)(s0 + 9) * 512], h1, l1);
        *(uint4*)(d_VB + (size_t)i * 4) = make_uint4(h0, h1, l0, l1);
    }
}

// ---------------- main ----------------
// CTA: 16 rows x 512 cols. 8 warps = 8 col-slices of 64. k2 = 0..3 (16 cols each).
__global__ void __launch_bounds__(256, 2) anomaly_mma(const float* __restrict__ Qg,
                                                      const float* __restrict__ SG,
                                                      float* __restrict__ out) {
    extern __shared__ char sm[];
    const uint32_t smb = s2u(sm);
    float* RS  = (float*)(sm + RS_OFF);
    float* INV = (float*)(sm + INV_OFF);

    const int tid = threadIdx.x, lane = tid & 31, wid = tid >> 5;
    const int g = lane >> 2, t = lane & 3;
    const int mt = blockIdx.x & 31;
    const int bh = blockIdx.x >> 5;
    const int h = bh & 7, b = bh >> 3;
    const int l0 = mt * 16;
    const int cq = wid;

    const uint32_t Aw = smb + A_OFF + wid * 8192;
    char* Awc = sm + A_OFF + wid * 8192;
    char* Bwc = sm + B_OFF + wid * 4096;

    const char* srcK = (const char*)d_KB + (size_t)(bh * 64 + cq * 8) * 2048;
    const char* srcV = (const char*)d_VB + (size_t)bh * 131072 + (size_t)cq * 2048;

    // kick off K prefetch for k2=0 before doing Q packing (overlap)
    #pragma unroll
    for (int n = 0; n < 2; n++)
        #pragma unroll
        for (int kt = 0; kt < 4; kt++)
            cp16(Aw + n * 2048 + kt * 512 + lane * 16,
                 srcK + n * 2048 + kt * 512 + lane * 16);
    cpcommit();

    // ---- Q fragments: direct fp32 load + split (replaces QA prepack) ----
    uint32_t qhi[4][4], qlo[4][4];
    {
        const float* qp = Qg + ((size_t)(b * SEQ + l0) * NHEAD + h) * HD;
        #pragma unroll
        for (int kt = 0; kt < 4; kt++) {
            const int e0 = kt * 16 + 2 * t;
            packhl(qp[(size_t)g * 512 + e0],           qp[(size_t)g * 512 + e0 + 1],       qhi[kt][0], qlo[kt][0]);
            packhl(qp[(size_t)(g + 8) * 512 + e0],     qp[(size_t)(g + 8) * 512 + e0 + 1], qhi[kt][1], qlo[kt][1]);
            packhl(qp[(size_t)g * 512 + e0 + 8],       qp[(size_t)g * 512 + e0 + 9],       qhi[kt][2], qlo[kt][2]);
            packhl(qp[(size_t)(g + 8) * 512 + e0 + 8], qp[(size_t)(g + 8) * 512 + e0 + 9], qhi[kt][3], qlo[kt][3]);
        }
    }

    // ================= loop1: GEMM1 -> exp -> stash P frags =================
    float rs0 = 0.f, rs1 = 0.f;
    #pragma unroll
    for (int k2 = 0; k2 < 4; k2++) {
        if (k2 < 3) {
            const int nb = (k2 + 1) & 1;
            #pragma unroll
            for (int n = 0; n < 2; n++)
                #pragma unroll
                for (int kt = 0; kt < 4; kt++)
                    cp16(Aw + nb * 4096 + n * 2048 + kt * 512 + lane * 16,
                         srcK + (size_t)(k2 + 1) * 4096 + n * 2048 + kt * 512 + lane * 16);
            cpcommit();
            cpwait1();
        } else {
            cpwait0();
        }

        const char* kb = Awc + (k2 & 1) * 4096;
        float aH[2][4], aX[2][4];
        #pragma unroll
        for (int n = 0; n < 2; n++)
            #pragma unroll
            for (int r = 0; r < 4; r++) { aH[n][r] = 0.f; aX[n][r] = 0.f; }

        #pragma unroll
        for (int n = 0; n < 2; n++) {
            #pragma unroll
            for (int kt = 0; kt < 4; kt++) {
                uint4 Bv = *(const uint4*)(kb + n * 2048 + kt * 512 + lane * 16);
                mma_bf16(aH[n], qhi[kt], Bv.x, Bv.y);
                mma_bf16(aX[n], qhi[kt], Bv.z, Bv.w);
                mma_bf16(aX[n], qlo[kt], Bv.x, Bv.y);
            }
        }

        float p[2][4];
        #pragma unroll
        for (int n = 0; n < 2; n++)
            #pragma unroll
            for (int r = 0; r < 4; r++)
                p[n][r] = __expf(0.125f * (aH[n][r] + aX[n][r]));

        rs0 += p[0][0] + p[0][1] + p[1][0] + p[1][1];
        rs1 += p[0][2] + p[0][3] + p[1][2] + p[1][3];

        uint32_t ah[4], al[4];
        packhl(p[0][0], p[0][1], ah[0], al[0]);
        packhl(p[0][2], p[0][3], ah[1], al[1]);
        packhl(p[1][0], p[1][1], ah[2], al[2]);
        packhl(p[1][2], p[1][3], ah[3], al[3]);

        *(uint4*)(Bwc + k2 * 1024 + lane * 16)       = make_uint4(ah[0], ah[1], ah[2], ah[3]);
        *(uint4*)(Bwc + k2 * 1024 + 512 + lane * 16) = make_uint4(al[0], al[1], al[2], al[3]);
    }

    // ---- V prologue prefetch: overlaps rowsum barrier + INV phase ----
    // Safe: this warp's loop1 reads are complete; buffer slot 0 belongs to this warp only.
    #pragma unroll
    for (int dt = 0; dt < 8; dt++)
        cp16(Aw + dt * 512 + lane * 16, srcV + dt * 16384 + lane * 16);
    cpcommit();

    // ---- rowsums -> inv ----
    rs0 += __shfl_xor_sync(0xffffffffu, rs0, 1);
    rs0 += __shfl_xor_sync(0xffffffffu, rs0, 2);
    rs1 += __shfl_xor_sync(0xffffffffu, rs1, 1);
    rs1 += __shfl_xor_sync(0xffffffffu, rs1, 2);
    if (t == 0) {
        RS[g * 8 + wid]       = rs0;
        RS[(g + 8) * 8 + wid] = rs1;
    }
    __syncthreads();
    if (tid < 16) {
        float s = 0.f;
        #pragma unroll
        for (int w = 0; w < 8; w++) s += RS[tid * 8 + w];
        INV[tid] = 1.0f / s;
    }
    __syncthreads();
    const float invg  = INV[g];
    const float invg8 = INV[g + 8];

    // ================= loop2: series stores + GEMM2 =================
    float vacc[8][4];
    #pragma unroll
    for (int dt = 0; dt < 8; dt++)
        #pragma unroll
        for (int r = 0; r < 4; r++) vacc[dt][r] = 0.f;

    float* ser = out + V_SIZE + ((size_t)bh * 512 + l0) * 512 + cq * 64;

    #pragma unroll
    for (int k2 = 0; k2 < 4; k2++) {
        if (k2 < 3) {
            const int nb = (k2 + 1) & 1;
            #pragma unroll
            for (int dt = 0; dt < 8; dt++)
                cp16(Aw + nb * 4096 + dt * 512 + lane * 16,
                     srcV + (size_t)(k2 + 1) * 512 + dt * 16384 + lane * 16);
            cpcommit();
            cpwait1();
        } else {
            cpwait0();
        }

        uint4 H = *(const uint4*)(Bwc + k2 * 1024 + lane * 16);
        uint4 L = *(const uint4*)(Bwc + k2 * 1024 + 512 + lane * 16);

        // series (normalized, streaming stores)
        {
            float* r0p = ser + (size_t)g * 512 + k2 * 16 + 2 * t;
            float* r1p = ser + (size_t)(g + 8) * 512 + k2 * 16 + 2 * t;
            __stcs((float2*)r0p,       serpair(H.x, L.x, invg));
            __stcs((float2*)(r0p + 8), serpair(H.z, L.z, invg));
            __stcs((float2*)r1p,       serpair(H.y, L.y, invg8));
            __stcs((float2*)(r1p + 8), serpair(H.w, L.w, invg8));
        }

        // GEMM2 accumulate (unnormalized P)
        const char* vb = Awc + (k2 & 1) * 4096;
        uint32_t ah[4] = {H.x, H.y, H.z, H.w};
        uint32_t al[4] = {L.x, L.y, L.z, L.w};
        #pragma unroll
        for (int dt = 0; dt < 8; dt++) {
            uint4 Bv = *(const uint4*)(vb + dt * 512 + lane * 16);
            mma_bf16(vacc[dt], ah, Bv.x, Bv.y);
            mma_bf16(vacc[dt], ah, Bv.z, Bv.w);
            mma_bf16(vacc[dt], al, Bv.x, Bv.y);
        }
    }

    // ---- V cross-warp reduction (region A reused for partials) ----
    // BARRIER FIRST: all warps must exit loop2 before region A is overwritten
    // with fp32 partials (round-5 NaN lesson).
    __syncthreads();
    {
        float* part = (float*)(sm + wid * 4096);
        #pragma unroll
        for (int dt = 0; dt < 8; dt++) {
            *(float2*)(part + g * 64 + dt * 8 + 2 * t) =
                make_float2(vacc[dt][0] * invg, vacc[dt][1] * invg);
            *(float2*)(part + (g + 8) * 64 + dt * 8 + 2 * t) =
                make_float2(vacc[dt][2] * invg8, vacc[dt][3] * invg8);
        }
        __syncthreads();
        const int d = tid & 63;
        #pragma unroll
        for (int it = 0; it < 4; it++) {
            const int row = (tid >> 6) + it * 4;
            float s = 0.f;
            #pragma unroll
            for (int w = 0; w < 8; w++)
                s += ((float*)(sm + w * 4096))[row * 64 + d];
            __stcs(out + (((size_t)b * SEQ + l0 + row) * NHEAD + h) * HD + d, s);
        }
    }

    // ---- prior (2 rows per warp; run-skip underflowed spans) ----
    {
        float amp_ = 0.f, ninv_ = 0.f;
        if (lane < 2) {
            int l = l0 + wid * 2 + lane;
            float x   = SG[((size_t)b * SEQ + l) * NHEAD + h];
            float smv = 1.0f / (1.0f + __expf(-5.0f * x));
            float yf  = smv + 1e-5f;
            float p3  = (float)exp((double)yf * 1.0986122886681098);
            float sig = p3 - 1.0f;
            amp_  = 0.3989422804014327f / sig;
            ninv_ = -1.0f / (2.0f * sig * sig);
        }
        float* priorBase = out + V_SIZE + SER_SIZE + ((size_t)bh * 512 + l0) * 512;
        #pragma unroll
        for (int rr = 0; rr < 2; rr++) {
            float amp  = __shfl_sync(0xffffffffu, amp_, rr);
            float ninv = __shfl_sync(0xffffffffu, ninv_, rr);
            const int l = l0 + wid * 2 + rr;
            float* pp = priorBase + (size_t)(wid * 2 + rr) * 512;
            const int s0 = lane * 16;
            int dhi = l - s0, dlo = l - (s0 + 15);
            int admin = (dlo <= 0 && dhi >= 0) ? 0 : min(abs(dlo), abs(dhi));
            if (ninv * (float)(admin * admin) < -87.0f) {
                float4 z = make_float4(0.f, 0.f, 0.f, 0.f);
                __stcs((float4*)(pp + s0),      z);
                __stcs((float4*)(pp + s0 + 4),  z);
                __stcs((float4*)(pp + s0 + 8),  z);
                __stcs((float4*)(pp + s0 + 12), z);
            } else {
                #pragma unroll
                for (int j4 = 0; j4 < 4; j4++) {
                    float d0 = (float)(l - (s0 + j4 * 4 + 0));
                    float d1 = (float)(l - (s0 + j4 * 4 + 1));
                    float d2 = (float)(l - (s0 + j4 * 4 + 2));
                    float d3 = (float)(l - (s0 + j4 * 4 + 3));
                    float4 o;
                    o.x = amp * __expf(ninv * d0 * d0);
                    o.y = amp * __expf(ninv * d1 * d1);
                    o.z = amp * __expf(ninv * d2 * d2);
                    o.w = amp * __expf(ninv * d3 * d3);
                    __stcs((float4*)(pp + s0 + j4 * 4), o);
                }
            }
        }
    }
}

extern "C" void kernel_launch(void* const* d_in, const int* in_sizes, int n_in,
                              void* d_out, int out_size) {
    (void)in_sizes; (void)n_in; (void)out_size;
    const float* q  = (const float*)d_in[0];
    const float* k  = (const float*)d_in[1];
    const float* v  = (const float*)d_in[2];
    const float* sg = (const float*)d_in[3];
    float* out = (float*)d_out;

    cudaFuncSetAttribute(anomaly_mma, cudaFuncAttributeMaxDynamicSharedMemorySize,
                         (int)SMEM_BYTES);

    prepack<<<PREN / 256, 256>>>(k, v);
    anomaly_mma<<<NBATCH * NHEAD * 32, 256, SMEM_BYTES>>>(q, sg, out);
}

// round 9
// speedup vs baseline: 1.1240x; 1.1240x over previous
#include <cuda_runtime.h>
#include <cuda_bf16.h>
#include <math.h>
#include <stdint.h>

#define NBATCH 32
#define NHEAD  8
#define SEQ    512
#define HD     64

constexpr size_t V_SIZE   = (size_t)NBATCH * SEQ * NHEAD * HD;     // 8388608
constexpr size_t SER_SIZE = (size_t)NBATCH * NHEAD * SEQ * SEQ;    // 67108864

// ---- prepacked fragment arrays (bf16 hi/lo, mma-fragment-major) ----
__device__ uint32_t d_KB[(size_t)256 * 64 * 4 * 32 * 4];
__device__ uint32_t d_VB[(size_t)256 * 8 * 32 * 32 * 4];
__device__ uint32_t d_QA[(size_t)256 * 32 * 4 * 32 * 8];

constexpr int KBN = 256 * 64 * 4 * 32;
constexpr int VBN = 256 * 8 * 32 * 32;
constexpr int QAN = 256 * 32 * 4 * 32;
constexpr int PREN = KBN + VBN + QAN;

// ---- smem layout (bytes) ----
// A: per-warp 8KB double buffer (K stiles loop1, V stiles loop2)
// B: per-warp 4KB P-frag stash; after loop2 reused (per-warp) as fp32 V-partials
constexpr uint32_t A_OFF  = 0;        // 8 * 8192  = 65536
constexpr uint32_t B_OFF  = 65536;    // 8 * 4096  = 32768
constexpr uint32_t RS_OFF = 98304;    // [16 rows][8 warps] f32
constexpr uint32_t INV_OFF = 98816;   // [16] f32
constexpr uint32_t SMEM_BYTES = 98944;

__device__ __forceinline__ uint32_t s2u(const void* p) {
    uint32_t a;
    asm("{ .reg .u64 t; cvta.to.shared.u64 t, %1; cvt.u32.u64 %0, t; }" : "=r"(a) : "l"(p));
    return a;
}
__device__ __forceinline__ void cp16(uint32_t dst, const void* src) {
    asm volatile("cp.async.cg.shared.global [%0], [%1], 16;" :: "r"(dst), "l"(src) : "memory");
}
__device__ __forceinline__ void cpcommit() {
    asm volatile("cp.async.commit_group;" ::: "memory");
}
__device__ __forceinline__ void cpwait0() {
    asm volatile("cp.async.wait_group 0;" ::: "memory");
}
__device__ __forceinline__ void cpwait1() {
    asm volatile("cp.async.wait_group 1;" ::: "memory");
}

__device__ __forceinline__ void packhl(float x0, float x1, uint32_t& hi, uint32_t& lo) {
    __nv_bfloat16 h0 = __float2bfloat16(x0);
    __nv_bfloat16 h1 = __float2bfloat16(x1);
    __nv_bfloat16 l0 = __float2bfloat16(x0 - __bfloat162float(h0));
    __nv_bfloat16 l1 = __float2bfloat16(x1 - __bfloat162float(h1));
    hi = (uint32_t)__bfloat16_as_ushort(h0) | ((uint32_t)__bfloat16_as_ushort(h1) << 16);
    lo = (uint32_t)__bfloat16_as_ushort(l0) | ((uint32_t)__bfloat16_as_ushort(l1) << 16);
}

__device__ __forceinline__ void mma_bf16(float* c, const uint32_t* a, uint32_t b0, uint32_t b1) {
    asm volatile(
        "mma.sync.aligned.m16n8k16.row.col.f32.bf16.bf16.f32 "
        "{%0,%1,%2,%3},{%4,%5,%6,%7},{%8,%9},{%0,%1,%2,%3};\n"
        : "+f"(c[0]), "+f"(c[1]), "+f"(c[2]), "+f"(c[3])
        : "r"(a[0]), "r"(a[1]), "r"(a[2]), "r"(a[3]), "r"(b0), "r"(b1));
}

__device__ __forceinline__ float2 serpair(uint32_t Hv, uint32_t Lv, float inv) {
    return make_float2(
        (__uint_as_float(Hv << 16) + __uint_as_float(Lv << 16)) * inv,
        (__uint_as_float(Hv & 0xffff0000u) + __uint_as_float(Lv & 0xffff0000u)) * inv);
}

// ---------------- prepack: Q, K, V fragments (round-6 version) ----------------
__global__ void __launch_bounds__(256) prepack(const float* __restrict__ Q,
                                               const float* __restrict__ K,
                                               const float* __restrict__ V) {
    int idx = blockIdx.x * 256 + threadIdx.x;
    int g = (idx >> 2) & 7, t = idx & 3;
    uint32_t h0, l0, h1, l1;
    if (idx < KBN) {
        int kt = (idx >> 5) & 3, st = (idx >> 7) & 63, bh = idx >> 13;
        int b = bh >> 3, h = bh & 7;
        int s = st * 8 + g, e0 = kt * 16 + 2 * t;
        const float* kp = K + (((size_t)b * SEQ + s) * NHEAD + h) * HD;
        packhl(kp[e0],     kp[e0 + 1], h0, l0);
        packhl(kp[e0 + 8], kp[e0 + 9], h1, l1);
        *(uint4*)(d_KB + (size_t)idx * 4) = make_uint4(h0, h1, l0, l1);
    } else if (idx < KBN + VBN) {
        int i = idx - KBN;
        int st = (i >> 5) & 31, dt = (i >> 10) & 7, bh = i >> 13;
        int b = bh >> 3, h = bh & 7;
        int s0 = st * 16 + 2 * t, d = dt * 8 + g;
        const float* vp = V + ((size_t)b * SEQ * NHEAD + h) * HD + d;
        packhl(vp[(size_t)s0 * 512],       vp[(size_t)(s0 + 1) * 512], h0, l0);
        packhl(vp[(size_t)(s0 + 8) * 512], vp[(size_t)(s0 + 9) * 512], h1, l1);
        *(uint4*)(d_VB + (size_t)i * 4) = make_uint4(h0, h1, l0, l1);
    } else if (idx < PREN) {
        int i = idx - KBN - VBN;
        int kt = (i >> 5) & 3, rt = (i >> 7) & 31, bh = i >> 12;
        int b = bh >> 3, h = bh & 7;
        int e0 = kt * 16 + 2 * t;
        const float* qp = Q + (((size_t)b * SEQ + rt * 16) * NHEAD + h) * HD;
        uint32_t ah[4], al[4];
        packhl(qp[(size_t)g * 512 + e0],           qp[(size_t)g * 512 + e0 + 1],       ah[0], al[0]);
        packhl(qp[(size_t)(g + 8) * 512 + e0],     qp[(size_t)(g + 8) * 512 + e0 + 1], ah[1], al[1]);
        packhl(qp[(size_t)g * 512 + e0 + 8],       qp[(size_t)g * 512 + e0 + 9],       ah[2], al[2]);
        packhl(qp[(size_t)(g + 8) * 512 + e0 + 8], qp[(size_t)(g + 8) * 512 + e0 + 9], ah[3], al[3]);
        *(uint4*)(d_QA + (size_t)i * 8)     = make_uint4(ah[0], ah[1], ah[2], ah[3]);
        *(uint4*)(d_QA + (size_t)i * 8 + 4) = make_uint4(al[0], al[1], al[2], al[3]);
    }
}

// ---------------- main ----------------
// CTA: 16 rows x 512 cols. 8 warps = 8 col-slices of 64. k2 = 0..3 (16 cols each).
__global__ void __launch_bounds__(256, 2) anomaly_mma(const float* __restrict__ SG,
                                                      float* __restrict__ out) {
    extern __shared__ char sm[];
    const uint32_t smb = s2u(sm);
    float* RS  = (float*)(sm + RS_OFF);
    float* INV = (float*)(sm + INV_OFF);

    const int tid = threadIdx.x, lane = tid & 31, wid = tid >> 5;
    const int g = lane >> 2, t = lane & 3;
    const int mt = blockIdx.x & 31;
    const int bh = blockIdx.x >> 5;
    const int h = bh & 7, b = bh >> 3;
    const int l0 = mt * 16;
    const int cq = wid;

    const uint32_t Aw = smb + A_OFF + wid * 8192;
    char* Awc = sm + A_OFF + wid * 8192;
    char* Bwc = sm + B_OFF + wid * 4096;

    const char* srcK = (const char*)d_KB + (size_t)(bh * 64 + cq * 8) * 2048;
    const char* srcV = (const char*)d_VB + (size_t)bh * 131072 + (size_t)cq * 2048;

    // kick K prefetch for k2=0 first, so it overlaps the QA register loads
    #pragma unroll
    for (int n = 0; n < 2; n++)
        #pragma unroll
        for (int kt = 0; kt < 4; kt++)
            cp16(Aw + n * 2048 + kt * 512 + lane * 16,
                 srcK + n * 2048 + kt * 512 + lane * 16);
    cpcommit();

    // ---- Q fragments (coalesced uint4 from QA prepack) ----
    uint32_t qhi[4][4], qlo[4][4];
    {
        const uint32_t* qa = d_QA + ((size_t)bh * 32 + mt) * 1024 + (size_t)lane * 8;
        #pragma unroll
        for (int kt = 0; kt < 4; kt++) {
            uint4 H = *(const uint4*)(qa + kt * 256);
            uint4 L = *(const uint4*)(qa + kt * 256 + 4);
            qhi[kt][0] = H.x; qhi[kt][1] = H.y; qhi[kt][2] = H.z; qhi[kt][3] = H.w;
            qlo[kt][0] = L.x; qlo[kt][1] = L.y; qlo[kt][2] = L.z; qlo[kt][3] = L.w;
        }
    }

    // ================= loop1: GEMM1 -> exp -> stash P frags =================
    float rs0 = 0.f, rs1 = 0.f;
    #pragma unroll
    for (int k2 = 0; k2 < 4; k2++) {
        if (k2 < 3) {
            const int nb = (k2 + 1) & 1;
            #pragma unroll
            for (int n = 0; n < 2; n++)
                #pragma unroll
                for (int kt = 0; kt < 4; kt++)
                    cp16(Aw + nb * 4096 + n * 2048 + kt * 512 + lane * 16,
                         srcK + (size_t)(k2 + 1) * 4096 + n * 2048 + kt * 512 + lane * 16);
            cpcommit();
            cpwait1();
        } else {
            cpwait0();
        }

        const char* kb = Awc + (k2 & 1) * 4096;
        float aH[2][4], aX[2][4];
        #pragma unroll
        for (int n = 0; n < 2; n++)
            #pragma unroll
            for (int r = 0; r < 4; r++) { aH[n][r] = 0.f; aX[n][r] = 0.f; }

        #pragma unroll
        for (int n = 0; n < 2; n++) {
            #pragma unroll
            for (int kt = 0; kt < 4; kt++) {
                uint4 Bv = *(const uint4*)(kb + n * 2048 + kt * 512 + lane * 16);
                mma_bf16(aH[n], qhi[kt], Bv.x, Bv.y);
                mma_bf16(aX[n], qhi[kt], Bv.z, Bv.w);
                mma_bf16(aX[n], qlo[kt], Bv.x, Bv.y);
            }
        }

        float p[2][4];
        #pragma unroll
        for (int n = 0; n < 2; n++)
            #pragma unroll
            for (int r = 0; r < 4; r++)
                p[n][r] = __expf(0.125f * (aH[n][r] + aX[n][r]));

        rs0 += p[0][0] + p[0][1] + p[1][0] + p[1][1];
        rs1 += p[0][2] + p[0][3] + p[1][2] + p[1][3];

        uint32_t ah[4], al[4];
        packhl(p[0][0], p[0][1], ah[0], al[0]);
        packhl(p[0][2], p[0][3], ah[1], al[1]);
        packhl(p[1][0], p[1][1], ah[2], al[2]);
        packhl(p[1][2], p[1][3], ah[3], al[3]);

        *(uint4*)(Bwc + k2 * 1024 + lane * 16)       = make_uint4(ah[0], ah[1], ah[2], ah[3]);
        *(uint4*)(Bwc + k2 * 1024 + 512 + lane * 16) = make_uint4(al[0], al[1], al[2], al[3]);
    }

    // ---- V prologue prefetch: overlaps rowsum barrier + INV phase ----
    #pragma unroll
    for (int dt = 0; dt < 8; dt++)
        cp16(Aw + dt * 512 + lane * 16, srcV + dt * 16384 + lane * 16);
    cpcommit();

    // ---- rowsums -> inv ----
    rs0 += __shfl_xor_sync(0xffffffffu, rs0, 1);
    rs0 += __shfl_xor_sync(0xffffffffu, rs0, 2);
    rs1 += __shfl_xor_sync(0xffffffffu, rs1, 1);
    rs1 += __shfl_xor_sync(0xffffffffu, rs1, 2);
    if (t == 0) {
        RS[g * 8 + wid]       = rs0;
        RS[(g + 8) * 8 + wid] = rs1;
    }
    __syncthreads();
    if (tid < 16) {
        float s = 0.f;
        #pragma unroll
        for (int w = 0; w < 8; w++) s += RS[tid * 8 + w];
        INV[tid] = 1.0f / s;
    }
    __syncthreads();
    const float invg  = INV[g];
    const float invg8 = INV[g + 8];

    // ================= loop2: series stores + GEMM2 =================
    float vacc[8][4];
    #pragma unroll
    for (int dt = 0; dt < 8; dt++)
        #pragma unroll
        for (int r = 0; r < 4; r++) vacc[dt][r] = 0.f;

    float* ser = out + V_SIZE + ((size_t)bh * 512 + l0) * 512 + cq * 64;

    #pragma unroll
    for (int k2 = 0; k2 < 4; k2++) {
        if (k2 < 3) {
            const int nb = (k2 + 1) & 1;
            #pragma unroll
            for (int dt = 0; dt < 8; dt++)
                cp16(Aw + nb * 4096 + dt * 512 + lane * 16,
                     srcV + (size_t)(k2 + 1) * 512 + dt * 16384 + lane * 16);
            cpcommit();
            cpwait1();
        } else {
            cpwait0();
        }

        uint4 H = *(const uint4*)(Bwc + k2 * 1024 + lane * 16);
        uint4 L = *(const uint4*)(Bwc + k2 * 1024 + 512 + lane * 16);

        // series (normalized, streaming stores)
        {
            float* r0p = ser + (size_t)g * 512 + k2 * 16 + 2 * t;
            float* r1p = ser + (size_t)(g + 8) * 512 + k2 * 16 + 2 * t;
            __stcs((float2*)r0p,       serpair(H.x, L.x, invg));
            __stcs((float2*)(r0p + 8), serpair(H.z, L.z, invg));
            __stcs((float2*)r1p,       serpair(H.y, L.y, invg8));
            __stcs((float2*)(r1p + 8), serpair(H.w, L.w, invg8));
        }

        // GEMM2 accumulate (unnormalized P)
        const char* vb = Awc + (k2 & 1) * 4096;
        uint32_t ah[4] = {H.x, H.y, H.z, H.w};
        uint32_t al[4] = {L.x, L.y, L.z, L.w};
        #pragma unroll
        for (int dt = 0; dt < 8; dt++) {
            uint4 Bv = *(const uint4*)(vb + dt * 512 + lane * 16);
            mma_bf16(vacc[dt], ah, Bv.x, Bv.y);
            mma_bf16(vacc[dt], ah, Bv.z, Bv.w);
            mma_bf16(vacc[dt], al, Bv.x, Bv.y);
        }
    }

    // ---- V cross-warp reduction via stash region (per-warp ownership: no pre-barrier) ----
    // After loop2 each warp has finished reading its OWN stash (program order), and no
    // other warp ever touches it -> safe to overwrite immediately with fp32 partials.
    {
        float* part = (float*)Bwc;   // 16 rows x 64 d x 4B = 4096B, exactly the stash
        #pragma unroll
        for (int dt = 0; dt < 8; dt++) {
            *(float2*)(part + g * 64 + dt * 8 + 2 * t) =
                make_float2(vacc[dt][0] * invg, vacc[dt][1] * invg);
            *(float2*)(part + (g + 8) * 64 + dt * 8 + 2 * t) =
                make_float2(vacc[dt][2] * invg8, vacc[dt][3] * invg8);
        }
        __syncthreads();   // all warps' partials visible
        const int d = tid & 63;
        #pragma unroll
        for (int it = 0; it < 4; it++) {
            const int row = (tid >> 6) + it * 4;
            float s = 0.f;
            #pragma unroll
            for (int w = 0; w < 8; w++)
                s += ((float*)(sm + B_OFF + w * 4096))[row * 64 + d];
            __stcs(out + (((size_t)b * SEQ + l0 + row) * NHEAD + h) * HD + d, s);
        }
    }

    // ---- prior (2 rows per warp; run-skip underflowed spans) ----
    {
        float amp_ = 0.f, ninv_ = 0.f;
        if (lane < 2) {
            int l = l0 + wid * 2 + lane;
            float x   = SG[((size_t)b * SEQ + l) * NHEAD + h];
            float smv = 1.0f / (1.0f + __expf(-5.0f * x));
            float yf  = smv + 1e-5f;
            float p3  = (float)exp((double)yf * 1.0986122886681098);
            float sig = p3 - 1.0f;
            amp_  = 0.3989422804014327f / sig;
            ninv_ = -1.0f / (2.0f * sig * sig);
        }
        float* priorBase = out + V_SIZE + SER_SIZE + ((size_t)bh * 512 + l0) * 512;
        #pragma unroll
        for (int rr = 0; rr < 2; rr++) {
            float amp  = __shfl_sync(0xffffffffu, amp_, rr);
            float ninv = __shfl_sync(0xffffffffu, ninv_, rr);
            const int l = l0 + wid * 2 + rr;
            float* pp = priorBase + (size_t)(wid * 2 + rr) * 512;
            const int s0 = lane * 16;
            int dhi = l - s0, dlo = l - (s0 + 15);
            int admin = (dlo <= 0 && dhi >= 0) ? 0 : min(abs(dlo), abs(dhi));
            if (ninv * (float)(admin * admin) < -87.0f) {
                float4 z = make_float4(0.f, 0.f, 0.f, 0.f);
                __stcs((float4*)(pp + s0),      z);
                __stcs((float4*)(pp + s0 + 4),  z);
                __stcs((float4*)(pp + s0 + 8),  z);
                __stcs((float4*)(pp + s0 + 12), z);
            } else {
                #pragma unroll
                for (int j4 = 0; j4 < 4; j4++) {
                    float d0 = (float)(l - (s0 + j4 * 4 + 0));
                    float d1 = (float)(l - (s0 + j4 * 4 + 1));
                    float d2 = (float)(l - (s0 + j4 * 4 + 2));
                    float d3 = (float)(l - (s0 + j4 * 4 + 3));
                    float4 o;
                    o.x = amp * __expf(ninv * d0 * d0);
                    o.y = amp * __expf(ninv * d1 * d1);
                    o.z = amp * __expf(ninv * d2 * d2);
                    o.w = amp * __expf(ninv * d3 * d3);
                    __stcs((float4*)(pp + s0 + j4 * 4), o);
                }
            }
        }
    }
}

extern "C" void kernel_launch(void* const* d_in, const int* in_sizes, int n_in,
                              void* d_out, int out_size) {
    (void)in_sizes; (void)n_in; (void)out_size;
    const float* q  = (const float*)d_in[0];
    const float* k  = (const float*)d_in[1];
    const float* v  = (const float*)d_in[2];
    const float* sg = (const float*)d_in[3];
    float* out = (float*)d_out;

    cudaFuncSetAttribute(anomaly_mma, cudaFuncAttributeMaxDynamicSharedMemorySize,
                         (int)SMEM_BYTES);

    prepack<<<PREN / 256, 256>>>(q, k, v);
    anomaly_mma<<<NBATCH * NHEAD * 32, 256, SMEM_BYTES>>>(sg, out);
}

// round 10
// speedup vs baseline: 1.1242x; 1.0002x over previous
#include <cuda_runtime.h>
#include <cuda_bf16.h>
#include <math.h>
#include <stdint.h>

#define NBATCH 32
#define NHEAD  8
#define SEQ    512
#define HD     64

constexpr size_t V_SIZE   = (size_t)NBATCH * SEQ * NHEAD * HD;     // 8388608
constexpr size_t SER_SIZE = (size_t)NBATCH * NHEAD * SEQ * SEQ;    // 67108864

// ---- prepacked tf32 fragment arrays (fragment-major, rna-rounded fp32 bits) ----
// KB: [bh 256][stile 64][kt 4][lane 32] uint4 {b0k0,b1k0,b0k1,b1k1}
// VB: [bh 256][dt 8][stile 32][lane 32] uint4
// QA: [bh 256][rtile 32][kt 4][lane 32] {uint4 kstep0 (a0..a3), uint4 kstep1}
__device__ uint32_t d_KB[(size_t)256 * 64 * 4 * 32 * 4];
__device__ uint32_t d_VB[(size_t)256 * 8 * 32 * 32 * 4];
__device__ uint32_t d_QA[(size_t)256 * 32 * 4 * 32 * 8];

constexpr int KBN = 256 * 64 * 4 * 32;
constexpr int VBN = 256 * 8 * 32 * 32;
constexpr int QAN = 256 * 32 * 4 * 32;
constexpr int PREN = KBN + VBN + QAN;

// ---- smem layout (bytes) ----
// A: per-warp 8KB double buffer (K stiles loop1, V stiles loop2)
// B: per-warp 4352B fp32 P stash [16 rows][stride 68 floats]; reused as V-partials
constexpr uint32_t A_OFF   = 0;        // 8 * 8192 = 65536
constexpr uint32_t B_OFF   = 65536;    // 8 * 4352 = 34816
constexpr uint32_t STASH_W = 4352;
constexpr uint32_t RS_OFF  = 100352;   // [16 rows][8 warps] f32
constexpr uint32_t INV_OFF = 100864;   // [16] f32
constexpr uint32_t SMEM_BYTES = 100928;

__device__ __forceinline__ uint32_t s2u(const void* p) {
    uint32_t a;
    asm("{ .reg .u64 t; cvta.to.shared.u64 t, %1; cvt.u32.u64 %0, t; }" : "=r"(a) : "l"(p));
    return a;
}
__device__ __forceinline__ void cp16(uint32_t dst, const void* src) {
    asm volatile("cp.async.cg.shared.global [%0], [%1], 16;" :: "r"(dst), "l"(src) : "memory");
}
__device__ __forceinline__ void cpcommit() { asm volatile("cp.async.commit_group;" ::: "memory"); }
__device__ __forceinline__ void cpwait0()  { asm volatile("cp.async.wait_group 0;" ::: "memory"); }
__device__ __forceinline__ void cpwait1()  { asm volatile("cp.async.wait_group 1;" ::: "memory"); }

// round-to-nearest tf32 (rna, NOT truncation: truncation biases dot products low)
__device__ __forceinline__ uint32_t rna(float x) {
    uint32_t r;
    asm("cvt.rna.tf32.f32 %0, %1;" : "=r"(r) : "f"(x));
    return r;
}

__device__ __forceinline__ void mma_tf32(float* c, const uint32_t* a, uint32_t b0, uint32_t b1) {
    asm volatile(
        "mma.sync.aligned.m16n8k8.row.col.f32.tf32.tf32.f32 "
        "{%0,%1,%2,%3},{%4,%5,%6,%7},{%8,%9},{%0,%1,%2,%3};\n"
        : "+f"(c[0]), "+f"(c[1]), "+f"(c[2]), "+f"(c[3])
        : "r"(a[0]), "r"(a[1]), "r"(a[2]), "r"(a[3]), "r"(b0), "r"(b1));
}

// ---------------- prepack: Q, K, V -> tf32 fragment-major ----------------
__global__ void __launch_bounds__(256) prepack(const float* __restrict__ Q,
                                               const float* __restrict__ K,
                                               const float* __restrict__ V) {
    int idx = blockIdx.x * 256 + threadIdx.x;
    int g = (idx >> 2) & 7, t = idx & 3;
    if (idx < KBN) {
        int kt = (idx >> 5) & 3, st = (idx >> 7) & 63, bh = idx >> 13;
        int b = bh >> 3, h = bh & 7;
        int s = st * 8 + g, k0 = kt * 16 + t;
        const float* kp = K + (((size_t)b * SEQ + s) * NHEAD + h) * HD;
        *(uint4*)(d_KB + (size_t)idx * 4) =
            make_uint4(rna(kp[k0]), rna(kp[k0 + 4]), rna(kp[k0 + 8]), rna(kp[k0 + 12]));
    } else if (idx < KBN + VBN) {
        int i = idx - KBN;
        int st = (i >> 5) & 31, dt = (i >> 10) & 7, bh = i >> 13;
        int b = bh >> 3, h = bh & 7;
        int d = dt * 8 + g, ks = st * 16 + t;
        const float* vp = V + ((size_t)b * SEQ * NHEAD + h) * HD + d;
        *(uint4*)(d_VB + (size_t)i * 4) =
            make_uint4(rna(vp[(size_t)ks * 512]),       rna(vp[(size_t)(ks + 4) * 512]),
                       rna(vp[(size_t)(ks + 8) * 512]), rna(vp[(size_t)(ks + 12) * 512]));
    } else if (idx < PREN) {
        int i = idx - KBN - VBN;
        int kt = (i >> 5) & 3, rt = (i >> 7) & 31, bh = i >> 12;
        int b = bh >> 3, h = bh & 7;
        int k0 = kt * 16 + t;
        const float* qp = Q + (((size_t)b * SEQ + rt * 16) * NHEAD + h) * HD;
        // kstep0: a0=(g,k0) a1=(g+8,k0) a2=(g,k0+4) a3=(g+8,k0+4); kstep1: +8
        *(uint4*)(d_QA + (size_t)i * 8) =
            make_uint4(rna(qp[(size_t)g * 512 + k0]),     rna(qp[(size_t)(g + 8) * 512 + k0]),
                       rna(qp[(size_t)g * 512 + k0 + 4]), rna(qp[(size_t)(g + 8) * 512 + k0 + 4]));
        *(uint4*)(d_QA + (size_t)i * 8 + 4) =
            make_uint4(rna(qp[(size_t)g * 512 + k0 + 8]),  rna(qp[(size_t)(g + 8) * 512 + k0 + 8]),
                       rna(qp[(size_t)g * 512 + k0 + 12]), rna(qp[(size_t)(g + 8) * 512 + k0 + 12]));
    }
}

// ---------------- main ----------------
// CTA: 16 rows x 512 cols. 8 warps = 8 col-slices of 64. k2 = 0..3 (16 cols each).
__global__ void __launch_bounds__(256, 2) anomaly_mma(const float* __restrict__ SG,
                                                      float* __restrict__ out) {
    extern __shared__ char sm[];
    const uint32_t smb = s2u(sm);
    float* RS  = (float*)(sm + RS_OFF);
    float* INV = (float*)(sm + INV_OFF);

    const int tid = threadIdx.x, lane = tid & 31, wid = tid >> 5;
    const int g = lane >> 2, t = lane & 3;
    const int mt = blockIdx.x & 31;
    const int bh = blockIdx.x >> 5;
    const int h = bh & 7, b = bh >> 3;
    const int l0 = mt * 16;
    const int cq = wid;

    const uint32_t Aw = smb + A_OFF + wid * 8192;
    char* Awc = sm + A_OFF + wid * 8192;
    float* stg = (float*)(sm + B_OFF + wid * STASH_W);   // [16][68] fp32 P stash

    const char* srcK = (const char*)d_KB + (size_t)(bh * 64 + cq * 8) * 2048;
    const char* srcV = (const char*)d_VB + (size_t)bh * 131072 + (size_t)cq * 2048;

    // kick K prefetch for k2=0 first, overlapping the QA loads
    #pragma unroll
    for (int n = 0; n < 2; n++)
        #pragma unroll
        for (int kt = 0; kt < 4; kt++)
            cp16(Aw + n * 2048 + kt * 512 + lane * 16,
                 srcK + n * 2048 + kt * 512 + lane * 16);
    cpcommit();

    // ---- Q fragments (tf32) for the CTA's 16 rows ----
    uint32_t qf[4][8];
    {
        const uint32_t* qa = d_QA + ((size_t)bh * 32 + mt) * 1024 + (size_t)lane * 8;
        #pragma unroll
        for (int kt = 0; kt < 4; kt++) {
            uint4 X = *(const uint4*)(qa + kt * 256);
            uint4 Y = *(const uint4*)(qa + kt * 256 + 4);
            qf[kt][0] = X.x; qf[kt][1] = X.y; qf[kt][2] = X.z; qf[kt][3] = X.w;
            qf[kt][4] = Y.x; qf[kt][5] = Y.y; qf[kt][6] = Y.z; qf[kt][7] = Y.w;
        }
    }

    // ================= loop1: GEMM1 (tf32) -> exp -> fp32 stash =================
    float rs0 = 0.f, rs1 = 0.f;
    #pragma unroll
    for (int k2 = 0; k2 < 4; k2++) {
        if (k2 < 3) {
            const int nb = (k2 + 1) & 1;
            #pragma unroll
            for (int n = 0; n < 2; n++)
                #pragma unroll
                for (int kt = 0; kt < 4; kt++)
                    cp16(Aw + nb * 4096 + n * 2048 + kt * 512 + lane * 16,
                         srcK + (size_t)(k2 + 1) * 4096 + n * 2048 + kt * 512 + lane * 16);
            cpcommit();
            cpwait1();
        } else {
            cpwait0();
        }

        const char* kb = Awc + (k2 & 1) * 4096;
        float aA[2][4], aB[2][4];   // even-kt / odd-kt accumulators (chain depth 4)
        #pragma unroll
        for (int n = 0; n < 2; n++)
            #pragma unroll
            for (int r = 0; r < 4; r++) { aA[n][r] = 0.f; aB[n][r] = 0.f; }

        #pragma unroll
        for (int n = 0; n < 2; n++) {
            #pragma unroll
            for (int kt = 0; kt < 4; kt++) {
                uint4 Bv = *(const uint4*)(kb + n * 2048 + kt * 512 + lane * 16);
                float* acc = (kt & 1) ? aB[n] : aA[n];
                mma_tf32(acc, &qf[kt][0], Bv.x, Bv.y);
                mma_tf32(acc, &qf[kt][4], Bv.z, Bv.w);
            }
        }

        float p[2][4];
        #pragma unroll
        for (int n = 0; n < 2; n++)
            #pragma unroll
            for (int r = 0; r < 4; r++)
                p[n][r] = __expf(0.125f * (aA[n][r] + aB[n][r]));

        rs0 += p[0][0] + p[0][1] + p[1][0] + p[1][1];
        rs1 += p[0][2] + p[0][3] + p[1][2] + p[1][3];

        // stash unnormalized fp32 p at true (row, col) positions, stride 68
        #pragma unroll
        for (int n = 0; n < 2; n++) {
            const int col = k2 * 16 + n * 8 + 2 * t;
            *(float2*)&stg[g * 68 + col]       = make_float2(p[n][0], p[n][1]);
            *(float2*)&stg[(g + 8) * 68 + col] = make_float2(p[n][2], p[n][3]);
        }
    }

    // ---- V prologue prefetch: overlaps rowsum barrier + INV phase ----
    #pragma unroll
    for (int dt = 0; dt < 8; dt++)
        cp16(Aw + dt * 512 + lane * 16, srcV + dt * 16384 + lane * 16);
    cpcommit();

    // ---- rowsums -> inv ----
    rs0 += __shfl_xor_sync(0xffffffffu, rs0, 1);
    rs0 += __shfl_xor_sync(0xffffffffu, rs0, 2);
    rs1 += __shfl_xor_sync(0xffffffffu, rs1, 1);
    rs1 += __shfl_xor_sync(0xffffffffu, rs1, 2);
    if (t == 0) {
        RS[g * 8 + wid]       = rs0;
        RS[(g + 8) * 8 + wid] = rs1;
    }
    __syncthreads();
    if (tid < 16) {
        float s = 0.f;
        #pragma unroll
        for (int w = 0; w < 8; w++) s += RS[tid * 8 + w];
        INV[tid] = 1.0f / s;
    }
    __syncthreads();
    const float invg  = INV[g];
    const float invg8 = INV[g + 8];

    // ================= loop2: series stores + GEMM2 (tf32) =================
    float vacc[8][4];
    #pragma unroll
    for (int dt = 0; dt < 8; dt++)
        #pragma unroll
        for (int r = 0; r < 4; r++) vacc[dt][r] = 0.f;

    float* ser = out + V_SIZE + ((size_t)bh * 512 + l0) * 512 + cq * 64;

    #pragma unroll
    for (int k2 = 0; k2 < 4; k2++) {
        if (k2 < 3) {
            const int nb = (k2 + 1) & 1;
            #pragma unroll
            for (int dt = 0; dt < 8; dt++)
                cp16(Aw + nb * 4096 + dt * 512 + lane * 16,
                     srcV + (size_t)(k2 + 1) * 512 + dt * 16384 + lane * 16);
            cpcommit();
            cpwait1();
        } else {
            cpwait0();
        }

        const int s0 = k2 * 16;

        // A fragments for two ksteps (conflict-free: banks 4g+t distinct)
        uint32_t ua[4], ub[4];
        ua[0] = rna(stg[g * 68 + s0 + t]);
        ua[1] = rna(stg[(g + 8) * 68 + s0 + t]);
        ua[2] = rna(stg[g * 68 + s0 + t + 4]);
        ua[3] = rna(stg[(g + 8) * 68 + s0 + t + 4]);
        ub[0] = rna(stg[g * 68 + s0 + 8 + t]);
        ub[1] = rna(stg[(g + 8) * 68 + s0 + 8 + t]);
        ub[2] = rna(stg[g * 68 + s0 + 8 + t + 4]);
        ub[3] = rna(stg[(g + 8) * 68 + s0 + 8 + t + 4]);

        // series (normalized fp32, streaming stores)
        {
            float2 s00 = *(float2*)&stg[g * 68 + s0 + 2 * t];
            float2 s01 = *(float2*)&stg[g * 68 + s0 + 8 + 2 * t];
            float2 s10 = *(float2*)&stg[(g + 8) * 68 + s0 + 2 * t];
            float2 s11 = *(float2*)&stg[(g + 8) * 68 + s0 + 8 + 2 * t];
            float* r0p = ser + (size_t)g * 512 + s0 + 2 * t;
            float* r1p = ser + (size_t)(g + 8) * 512 + s0 + 2 * t;
            __stcs((float2*)r0p,       make_float2(s00.x * invg,  s00.y * invg));
            __stcs((float2*)(r0p + 8), make_float2(s01.x * invg,  s01.y * invg));
            __stcs((float2*)r1p,       make_float2(s10.x * invg8, s10.y * invg8));
            __stcs((float2*)(r1p + 8), make_float2(s11.x * invg8, s11.y * invg8));
        }

        // GEMM2 accumulate (unnormalized P)
        const char* vb = Awc + (k2 & 1) * 4096;
        #pragma unroll
        for (int dt = 0; dt < 8; dt++) {
            uint4 Bv = *(const uint4*)(vb + dt * 512 + lane * 16);
            mma_tf32(vacc[dt], ua, Bv.x, Bv.y);
            mma_tf32(vacc[dt], ub, Bv.z, Bv.w);
        }
    }

    // ---- V cross-warp reduction via stash region (per-warp ownership) ----
    {
        float* part = stg;   // 16 x 64 fp32 = 4096B <= STASH_W
        #pragma unroll
        for (int dt = 0; dt < 8; dt++) {
            *(float2*)(part + g * 64 + dt * 8 + 2 * t) =
                make_float2(vacc[dt][0] * invg, vacc[dt][1] * invg);
            *(float2*)(part + (g + 8) * 64 + dt * 8 + 2 * t) =
                make_float2(vacc[dt][2] * invg8, vacc[dt][3] * invg8);
        }
        __syncthreads();
        const int d = tid & 63;
        #pragma unroll
        for (int it = 0; it < 4; it++) {
            const int row = (tid >> 6) + it * 4;
            float s = 0.f;
            #pragma unroll
            for (int w = 0; w < 8; w++)
                s += ((float*)(sm + B_OFF + w * STASH_W))[row * 64 + d];
            __stcs(out + (((size_t)b * SEQ + l0 + row) * NHEAD + h) * HD + d, s);
        }
    }

    // ---- prior (2 rows per warp; run-skip underflowed spans) ----
    {
        float amp_ = 0.f, ninv_ = 0.f;
        if (lane < 2) {
            int l = l0 + wid * 2 + lane;
            float x   = SG[((size_t)b * SEQ + l) * NHEAD + h];
            float smv = 1.0f / (1.0f + __expf(-5.0f * x));
            float yf  = smv + 1e-5f;
            float p3  = (float)exp((double)yf * 1.0986122886681098);
            float sig = p3 - 1.0f;
            amp_  = 0.3989422804014327f / sig;
            ninv_ = -1.0f / (2.0f * sig * sig);
        }
        float* priorBase = out + V_SIZE + SER_SIZE + ((size_t)bh * 512 + l0) * 512;
        #pragma unroll
        for (int rr = 0; rr < 2; rr++) {
            float amp  = __shfl_sync(0xffffffffu, amp_, rr);
            float ninv = __shfl_sync(0xffffffffu, ninv_, rr);
            const int l = l0 + wid * 2 + rr;
            float* pp = priorBase + (size_t)(wid * 2 + rr) * 512;
            const int s0 = lane * 16;
            int dhi = l - s0, dlo = l - (s0 + 15);
            int admin = (dlo <= 0 && dhi >= 0) ? 0 : min(abs(dlo), abs(dhi));
            if (ninv * (float)(admin * admin) < -87.0f) {
                float4 z = make_float4(0.f, 0.f, 0.f, 0.f);
                __stcs((float4*)(pp + s0),      z);
                __stcs((float4*)(pp + s0 + 4),  z);
                __stcs((float4*)(pp + s0 + 8),  z);
                __stcs((float4*)(pp + s0 + 12), z);
            } else {
                #pragma unroll
                for (int j4 = 0; j4 < 4; j4++) {
                    float d0 = (float)(l - (s0 + j4 * 4 + 0));
                    float d1 = (float)(l - (s0 + j4 * 4 + 1));
                    float d2 = (float)(l - (s0 + j4 * 4 + 2));
                    float d3 = (float)(l - (s0 + j4 * 4 + 3));
                    float4 o;
                    o.x = amp * __expf(ninv * d0 * d0);
                    o.y = amp * __expf(ninv * d1 * d1);
                    o.z = amp * __expf(ninv * d2 * d2);
                    o.w = amp * __expf(ninv * d3 * d3);
                    __stcs((float4*)(pp + s0 + j4 * 4), o);
                }
            }
        }
    }
}

extern "C" void kernel_launch(void* const* d_in, const int* in_sizes, int n_in,
                              void* d_out, int out_size) {
    (void)in_sizes; (void)n_in; (void)out_size;
    const float* q  = (const float*)d_in[0];
    const float* k  = (const float*)d_in[1];
    const float* v  = (const float*)d_in[2];
    const float* sg = (const float*)d_in[3];
    float* out = (float*)d_out;

    cudaFuncSetAttribute(anomaly_mma, cudaFuncAttributeMaxDynamicSharedMemorySize,
                         (int)SMEM_BYTES);

    prepack<<<PREN / 256, 256>>>(q, k, v);
    anomaly_mma<<<NBATCH * NHEAD * 32, 256, SMEM_BYTES>>>(sg, out);
}

// round 11
// speedup vs baseline: 1.3277x; 1.1810x over previous
#include <cuda_runtime.h>
#include <cuda_bf16.h>
#include <math.h>
#include <stdint.h>

#define NBATCH 32
#define NHEAD  8
#define SEQ    512
#define HD     64

constexpr size_t V_SIZE   = (size_t)NBATCH * SEQ * NHEAD * HD;     // 8388608
constexpr size_t SER_SIZE = (size_t)NBATCH * NHEAD * SEQ * SEQ;    // 67108864

// ---- prepacked tf32 fragment arrays (fragment-major, rna-rounded fp32 bits) ----
__device__ uint32_t d_KB[(size_t)256 * 64 * 4 * 32 * 4];
__device__ uint32_t d_VB[(size_t)256 * 8 * 32 * 32 * 4];
__device__ uint32_t d_QA[(size_t)256 * 32 * 4 * 32 * 8];

constexpr int KBN = 256 * 64 * 4 * 32;
constexpr int VBN = 256 * 8 * 32 * 32;
constexpr int QAN = 256 * 32 * 4 * 32;
constexpr int PREN = KBN + VBN + QAN;

// ---- smem layout (bytes) ----
constexpr uint32_t A_OFF   = 0;        // 8 * 8192 = 65536 (per-warp K/V double buffer)
constexpr uint32_t B_OFF   = 65536;    // 8 * 4352 = 34816 (per-warp fp32 P stash [16][68])
constexpr uint32_t STASH_W = 4352;
constexpr uint32_t RS_OFF  = 100352;
constexpr uint32_t INV_OFF = 100864;
constexpr uint32_t SMEM_BYTES = 100928;

__device__ __forceinline__ uint32_t s2u(const void* p) {
    uint32_t a;
    asm("{ .reg .u64 t; cvta.to.shared.u64 t, %1; cvt.u32.u64 %0, t; }" : "=r"(a) : "l"(p));
    return a;
}
__device__ __forceinline__ void cp16(uint32_t dst, const void* src) {
    asm volatile("cp.async.cg.shared.global [%0], [%1], 16;" :: "r"(dst), "l"(src) : "memory");
}
__device__ __forceinline__ void cpcommit() { asm volatile("cp.async.commit_group;" ::: "memory"); }
__device__ __forceinline__ void cpwait0()  { asm volatile("cp.async.wait_group 0;" ::: "memory"); }
__device__ __forceinline__ void cpwait1()  { asm volatile("cp.async.wait_group 1;" ::: "memory"); }

// round-to-nearest tf32 (rna; truncation would bias dot products)
__device__ __forceinline__ uint32_t rna(float x) {
    uint32_t r;
    asm("cvt.rna.tf32.f32 %0, %1;" : "=r"(r) : "f"(x));
    return r;
}

__device__ __forceinline__ void mma_tf32(float* c, const uint32_t* a, uint32_t b0, uint32_t b1) {
    asm volatile(
        "mma.sync.aligned.m16n8k8.row.col.f32.tf32.tf32.f32 "
        "{%0,%1,%2,%3},{%4,%5,%6,%7},{%8,%9},{%0,%1,%2,%3};\n"
        : "+f"(c[0]), "+f"(c[1]), "+f"(c[2]), "+f"(c[3])
        : "r"(a[0]), "r"(a[1]), "r"(a[2]), "r"(a[3]), "r"(b0), "r"(b1));
}

// ---------------- prepack (unchanged from round 10) ----------------
__global__ void __launch_bounds__(256) prepack(const float* __restrict__ Q,
                                               const float* __restrict__ K,
                                               const float* __restrict__ V) {
    int idx = blockIdx.x * 256 + threadIdx.x;
    int g = (idx >> 2) & 7, t = idx & 3;
    if (idx < KBN) {
        int kt = (idx >> 5) & 3, st = (idx >> 7) & 63, bh = idx >> 13;
        int b = bh >> 3, h = bh & 7;
        int s = st * 8 + g, k0 = kt * 16 + t;
        const float* kp = K + (((size_t)b * SEQ + s) * NHEAD + h) * HD;
        *(uint4*)(d_KB + (size_t)idx * 4) =
            make_uint4(rna(kp[k0]), rna(kp[k0 + 4]), rna(kp[k0 + 8]), rna(kp[k0 + 12]));
    } else if (idx < KBN + VBN) {
        int i = idx - KBN;
        int st = (i >> 5) & 31, dt = (i >> 10) & 7, bh = i >> 13;
        int b = bh >> 3, h = bh & 7;
        int d = dt * 8 + g, ks = st * 16 + t;
        const float* vp = V + ((size_t)b * SEQ * NHEAD + h) * HD + d;
        *(uint4*)(d_VB + (size_t)i * 4) =
            make_uint4(rna(vp[(size_t)ks * 512]),       rna(vp[(size_t)(ks + 4) * 512]),
                       rna(vp[(size_t)(ks + 8) * 512]), rna(vp[(size_t)(ks + 12) * 512]));
    } else if (idx < PREN) {
        int i = idx - KBN - VBN;
        int kt = (i >> 5) & 3, rt = (i >> 7) & 31, bh = i >> 12;
        int b = bh >> 3, h = bh & 7;
        int k0 = kt * 16 + t;
        const float* qp = Q + (((size_t)b * SEQ + rt * 16) * NHEAD + h) * HD;
        *(uint4*)(d_QA + (size_t)i * 8) =
            make_uint4(rna(qp[(size_t)g * 512 + k0]),     rna(qp[(size_t)(g + 8) * 512 + k0]),
                       rna(qp[(size_t)g * 512 + k0 + 4]), rna(qp[(size_t)(g + 8) * 512 + k0 + 4]));
        *(uint4*)(d_QA + (size_t)i * 8 + 4) =
            make_uint4(rna(qp[(size_t)g * 512 + k0 + 8]),  rna(qp[(size_t)(g + 8) * 512 + k0 + 8]),
                       rna(qp[(size_t)g * 512 + k0 + 12]), rna(qp[(size_t)(g + 8) * 512 + k0 + 12]));
    }
}

// ---------------- main ----------------
// CTA: 16 rows x 512 cols. 8 warps = 8 col-slices of 64.
__global__ void __launch_bounds__(256, 2) anomaly_mma(const float* __restrict__ SG,
                                                      float* __restrict__ out) {
    extern __shared__ char sm[];
    const uint32_t smb = s2u(sm);
    float* RS  = (float*)(sm + RS_OFF);
    float* INV = (float*)(sm + INV_OFF);

    const int tid = threadIdx.x, lane = tid & 31, wid = tid >> 5;
    const int g = lane >> 2, t = lane & 3;
    const int mt = blockIdx.x & 31;
    const int bh = blockIdx.x >> 5;
    const int h = bh & 7, b = bh >> 3;
    const int l0 = mt * 16;
    const int cq = wid;

    const uint32_t Aw = smb + A_OFF + wid * 8192;
    char* Awc = sm + A_OFF + wid * 8192;
    float* stg = (float*)(sm + B_OFF + wid * STASH_W);

    const char* srcK = (const char*)d_KB + (size_t)(bh * 64 + cq * 8) * 2048;
    const char* srcV = (const char*)d_VB + (size_t)bh * 131072 + (size_t)cq * 2048;

    #pragma unroll
    for (int n = 0; n < 2; n++)
        #pragma unroll
        for (int kt = 0; kt < 4; kt++)
            cp16(Aw + n * 2048 + kt * 512 + lane * 16,
                 srcK + n * 2048 + kt * 512 + lane * 16);
    cpcommit();

    // ---- Q fragments (tf32) ----
    uint32_t qf[4][8];
    {
        const uint32_t* qa = d_QA + ((size_t)bh * 32 + mt) * 1024 + (size_t)lane * 8;
        #pragma unroll
        for (int kt = 0; kt < 4; kt++) {
            uint4 X = *(const uint4*)(qa + kt * 256);
            uint4 Y = *(const uint4*)(qa + kt * 256 + 4);
            qf[kt][0] = X.x; qf[kt][1] = X.y; qf[kt][2] = X.z; qf[kt][3] = X.w;
            qf[kt][4] = Y.x; qf[kt][5] = Y.y; qf[kt][6] = Y.z; qf[kt][7] = Y.w;
        }
    }

    // ================= loop1: GEMM1 (tf32) -> exp -> fp32 stash =================
    float rs0 = 0.f, rs1 = 0.f;
    #pragma unroll
    for (int k2 = 0; k2 < 4; k2++) {
        if (k2 < 3) {
            const int nb = (k2 + 1) & 1;
            #pragma unroll
            for (int n = 0; n < 2; n++)
                #pragma unroll
                for (int kt = 0; kt < 4; kt++)
                    cp16(Aw + nb * 4096 + n * 2048 + kt * 512 + lane * 16,
                         srcK + (size_t)(k2 + 1) * 4096 + n * 2048 + kt * 512 + lane * 16);
            cpcommit();
            cpwait1();
        } else {
            cpwait0();
        }

        const char* kb = Awc + (k2 & 1) * 4096;
        float aA[2][4], aB[2][4];
        #pragma unroll
        for (int n = 0; n < 2; n++)
            #pragma unroll
            for (int r = 0; r < 4; r++) { aA[n][r] = 0.f; aB[n][r] = 0.f; }

        #pragma unroll
        for (int n = 0; n < 2; n++) {
            #pragma unroll
            for (int kt = 0; kt < 4; kt++) {
                uint4 Bv = *(const uint4*)(kb + n * 2048 + kt * 512 + lane * 16);
                float* acc = (kt & 1) ? aB[n] : aA[n];
                mma_tf32(acc, &qf[kt][0], Bv.x, Bv.y);
                mma_tf32(acc, &qf[kt][4], Bv.z, Bv.w);
            }
        }

        float p[2][4];
        #pragma unroll
        for (int n = 0; n < 2; n++)
            #pragma unroll
            for (int r = 0; r < 4; r++)
                p[n][r] = __expf(0.125f * (aA[n][r] + aB[n][r]));

        rs0 += p[0][0] + p[0][1] + p[1][0] + p[1][1];
        rs1 += p[0][2] + p[0][3] + p[1][2] + p[1][3];

        #pragma unroll
        for (int n = 0; n < 2; n++) {
            const int col = k2 * 16 + n * 8 + 2 * t;
            *(float2*)&stg[g * 68 + col]       = make_float2(p[n][0], p[n][1]);
            *(float2*)&stg[(g + 8) * 68 + col] = make_float2(p[n][2], p[n][3]);
        }
    }

    // ---- V prologue prefetch (overlaps barrier phase) ----
    #pragma unroll
    for (int dt = 0; dt < 8; dt++)
        cp16(Aw + dt * 512 + lane * 16, srcV + dt * 16384 + lane * 16);
    cpcommit();

    // ---- rowsums -> inv ----
    rs0 += __shfl_xor_sync(0xffffffffu, rs0, 1);
    rs0 += __shfl_xor_sync(0xffffffffu, rs0, 2);
    rs1 += __shfl_xor_sync(0xffffffffu, rs1, 1);
    rs1 += __shfl_xor_sync(0xffffffffu, rs1, 2);
    if (t == 0) {
        RS[g * 8 + wid]       = rs0;
        RS[(g + 8) * 8 + wid] = rs1;
    }
    __syncthreads();
    if (tid < 16) {
        float s = 0.f;
        #pragma unroll
        for (int w = 0; w < 8; w++) s += RS[tid * 8 + w];
        INV[tid] = 1.0f / s;
    }
    __syncthreads();
    const float invg  = INV[g];
    const float invg8 = INV[g + 8];

    // ================= loop2: GEMM2 only (series store moved out) =================
    float vacc[8][4];
    #pragma unroll
    for (int dt = 0; dt < 8; dt++)
        #pragma unroll
        for (int r = 0; r < 4; r++) vacc[dt][r] = 0.f;

    #pragma unroll
    for (int k2 = 0; k2 < 4; k2++) {
        if (k2 < 3) {
            const int nb = (k2 + 1) & 1;
            #pragma unroll
            for (int dt = 0; dt < 8; dt++)
                cp16(Aw + nb * 4096 + dt * 512 + lane * 16,
                     srcV + (size_t)(k2 + 1) * 512 + dt * 16384 + lane * 16);
            cpcommit();
            cpwait1();
        } else {
            cpwait0();
        }

        const int s0 = k2 * 16;
        uint32_t ua[4], ub[4];
        ua[0] = rna(stg[g * 68 + s0 + t]);
        ua[1] = rna(stg[(g + 8) * 68 + s0 + t]);
        ua[2] = rna(stg[g * 68 + s0 + t + 4]);
        ua[3] = rna(stg[(g + 8) * 68 + s0 + t + 4]);
        ub[0] = rna(stg[g * 68 + s0 + 8 + t]);
        ub[1] = rna(stg[(g + 8) * 68 + s0 + 8 + t]);
        ub[2] = rna(stg[g * 68 + s0 + 8 + t + 4]);
        ub[3] = rna(stg[(g + 8) * 68 + s0 + 8 + t + 4]);

        const char* vb = Awc + (k2 & 1) * 4096;
        #pragma unroll
        for (int dt = 0; dt < 8; dt++) {
            uint4 Bv = *(const uint4*)(vb + dt * 512 + lane * 16);
            mma_tf32(vacc[dt], ua, Bv.x, Bv.y);
            mma_tf32(vacc[dt], ub, Bv.z, Bv.w);
        }
    }

    // ---- series write pass: coalesced 256B contiguous per row-slice ----
    {
        float* ser = out + V_SIZE + ((size_t)bh * 512 + l0) * 512 + cq * 64;
        #pragma unroll
        for (int r = 0; r < 16; r++) {
            float2 v = *(float2*)&stg[r * 68 + lane * 2];
            const float iv = INV[r];
            __stcs((float2*)(ser + (size_t)r * 512 + lane * 2),
                   make_float2(v.x * iv, v.y * iv));
        }
    }

    // ---- V cross-warp reduction via stash region (after series pass reads it) ----
    {
        float* part = stg;
        #pragma unroll
        for (int dt = 0; dt < 8; dt++) {
            *(float2*)(part + g * 64 + dt * 8 + 2 * t) =
                make_float2(vacc[dt][0] * invg, vacc[dt][1] * invg);
            *(float2*)(part + (g + 8) * 64 + dt * 8 + 2 * t) =
                make_float2(vacc[dt][2] * invg8, vacc[dt][3] * invg8);
        }
        __syncthreads();
        const int d = tid & 63;
        #pragma unroll
        for (int it = 0; it < 4; it++) {
            const int row = (tid >> 6) + it * 4;
            float s = 0.f;
            #pragma unroll
            for (int w = 0; w < 8; w++)
                s += ((float*)(sm + B_OFF + w * STASH_W))[row * 64 + d];
            __stcs(out + (((size_t)b * SEQ + l0 + row) * NHEAD + h) * HD + d, s);
        }
    }

    // ---- prior: warp sweeps 128-col chunks, lane*4 contiguous (coalesced);
    //      run-skip is warp-uniform per chunk ----
    {
        float amp_ = 0.f, ninv_ = 0.f;
        if (lane < 2) {
            int l = l0 + wid * 2 + lane;
            float x   = SG[((size_t)b * SEQ + l) * NHEAD + h];
            float smv = 1.0f / (1.0f + __expf(-5.0f * x));
            float yf  = smv + 1e-5f;
            float p3  = (float)exp((double)yf * 1.0986122886681098);
            float sig = p3 - 1.0f;
            amp_  = 0.3989422804014327f / sig;
            ninv_ = -1.0f / (2.0f * sig * sig);
        }
        float* priorBase = out + V_SIZE + SER_SIZE + ((size_t)bh * 512 + l0) * 512;
        #pragma unroll
        for (int rr = 0; rr < 2; rr++) {
            const float amp  = __shfl_sync(0xffffffffu, amp_, rr);
            const float ninv = __shfl_sync(0xffffffffu, ninv_, rr);
            const int l = l0 + wid * 2 + rr;
            float* pp = priorBase + (size_t)(wid * 2 + rr) * 512;
            #pragma unroll
            for (int j = 0; j < 4; j++) {
                const int c0 = j * 128;
                int dh = l - c0, dl = l - (c0 + 127);
                int admin = (dl <= 0 && dh >= 0) ? 0 : min(abs(dl), abs(dh));
                float* dst = pp + c0 + lane * 4;
                if (ninv * (float)(admin * admin) < -87.0f) {
                    __stcs((float4*)dst, make_float4(0.f, 0.f, 0.f, 0.f));
                } else {
                    const int s = c0 + lane * 4;
                    float d0 = (float)(l - s);
                    float d1 = (float)(l - (s + 1));
                    float d2 = (float)(l - (s + 2));
                    float d3 = (float)(l - (s + 3));
                    float4 o;
                    o.x = amp * __expf(ninv * d0 * d0);
                    o.y = amp * __expf(ninv * d1 * d1);
                    o.z = amp * __expf(ninv * d2 * d2);
                    o.w = amp * __expf(ninv * d3 * d3);
                    __stcs((float4*)dst, o);
                }
            }
        }
    }
}

extern "C" void kernel_launch(void* const* d_in, const int* in_sizes, int n_in,
                              void* d_out, int out_size) {
    (void)in_sizes; (void)n_in; (void)out_size;
    const float* q  = (const float*)d_in[0];
    const float* k  = (const float*)d_in[1];
    const float* v  = (const float*)d_in[2];
    const float* sg = (const float*)d_in[3];
    float* out = (float*)d_out;

    cudaFuncSetAttribute(anomaly_mma, cudaFuncAttributeMaxDynamicSharedMemorySize,
                         (int)SMEM_BYTES);

    prepack<<<PREN / 256, 256>>>(q, k, v);
    anomaly_mma<<<NBATCH * NHEAD * 32, 256, SMEM_BYTES>>>(sg, out);
}